// round 11
// baseline (speedup 1.0000x reference)
#include <cuda_runtime.h>
#include <math.h>

// Fused kernel: each block redundantly computes the circulant filter K
// (K[d] = Re(IFFT4(filt))[d]) in warp 0 while the streaming loads are in
// flight, then applies the 4x4 circulant matvec to VEC float4s per thread.
// Loads/stores use streaming cache hints (no reuse -> evict-first).
#define VEC 8

__device__ __forceinline__ float4 circ_matvec(float4 q, float k0, float k1,
                                              float k2, float k3) {
    float4 y;
    // out[n] = sum_m x[m] * K[(n-m) & 3]
    y.x = k0 * q.x + k3 * q.y + k2 * q.z + k1 * q.w;
    y.y = k1 * q.x + k0 * q.y + k3 * q.z + k2 * q.w;
    y.z = k2 * q.x + k1 * q.y + k0 * q.z + k3 * q.w;
    y.w = k3 * q.x + k2 * q.y + k1 * q.z + k0 * q.w;
    return y;
}

__global__ void __launch_bounds__(256, 6)
fused_filter_kernel(const float4* __restrict__ in,
                    float4* __restrict__ out,
                    const float* __restrict__ amp,
                    const float* __restrict__ phase,
                    int n4) {
    __shared__ float sK[4];

    const int span = blockDim.x * VEC;
    const int blk0 = blockIdx.x * span;
    const int base = blk0 + threadIdx.x;
    const bool fast = (blk0 + span <= n4);

    // ---- Issue streaming loads FIRST (independent of K) ----
    float4 x[VEC];
    if (fast) {
        #pragma unroll
        for (int v = 0; v < VEC; v++) x[v] = __ldcs(&in[base + v * blockDim.x]);
    } else {
        #pragma unroll
        for (int v = 0; v < VEC; v++) {
            int i = base + v * blockDim.x;
            if (i < n4) x[v] = __ldcs(&in[i]);
        }
    }

    // ---- Warp 0 computes K while loads are in flight ----
    if (threadIdx.x < 32) {
        const int lane = threadIdx.x;
        const float primes[24] = {2.f,3.f,5.f,7.f,11.f,13.f,17.f,19.f,23.f,29.f,
                                  31.f,37.f,41.f,43.f,47.f,53.f,59.f,61.f,67.f,
                                  71.f,73.f,79.f,83.f,89.f};
        const float PI = 3.14159265358979323846f;

        float re[4] = {0.f, 0.f, 0.f, 0.f};
        float im[4] = {0.f, 0.f, 0.f, 0.f};

        if (lane < 24) {
            float pf = primes[lane] / 89.0f * PI;   // prime freq in [0, pi]
            float a  = amp[lane];
            float ph = phase[lane];
            float cr = __cosf(ph);
            float ci = __sinf(ph);
            #pragma unroll
            for (int j = 0; j < 4; j++) {
                float fi = (float)j * 0.25f * PI;
                float d  = (fi - pf) * 10.0f;       // sigma = 0.1
                float g  = __expf(-0.5f * d * d);
                float w  = a * g;
                re[j] = w * cr;
                im[j] = w * ci;
            }
        }

        // butterfly reduction over the warp
        #pragma unroll
        for (int off = 16; off > 0; off >>= 1) {
            #pragma unroll
            for (int j = 0; j < 4; j++) {
                re[j] += __shfl_xor_sync(0xFFFFFFFFu, re[j], off);
                im[j] += __shfl_xor_sync(0xFFFFFFFFu, im[j], off);
            }
        }

        if (lane == 0) {
            // normalize by max complex magnitude
            float mx = 0.f;
            #pragma unroll
            for (int j = 0; j < 4; j++) {
                float m = sqrtf(re[j] * re[j] + im[j] * im[j]);
                mx = fmaxf(mx, m);
            }
            float inv = 1.0f / (mx + 1e-8f);
            #pragma unroll
            for (int j = 0; j < 4; j++) { re[j] *= inv; im[j] *= inv; }

            // K[d] = (1/4) * Re( sum_j filt[j] * e^{+i*2*pi*j*d/4} )
            // twiddles at multiples of pi/2 exact: cos->{1,0,-1,0}, sin->{0,1,0,-1}
            const float c4[4] = {1.f, 0.f, -1.f, 0.f};
            const float s4[4] = {0.f, 1.f, 0.f, -1.f};
            #pragma unroll
            for (int d = 0; d < 4; d++) {
                float s = 0.f;
                #pragma unroll
                for (int j = 0; j < 4; j++) {
                    int t = (j * d) & 3;
                    s += re[j] * c4[t] - im[j] * s4[t];
                }
                sK[d] = 0.25f * s;
            }
        }
    }
    __syncthreads();

    const float k0 = sK[0], k1 = sK[1], k2 = sK[2], k3 = sK[3];

    // ---- Apply + streaming store ----
    if (fast) {
        #pragma unroll
        for (int v = 0; v < VEC; v++)
            __stcs(&out[base + v * blockDim.x], circ_matvec(x[v], k0, k1, k2, k3));
    } else {
        #pragma unroll
        for (int v = 0; v < VEC; v++) {
            int i = base + v * blockDim.x;
            if (i < n4) __stcs(&out[i], circ_matvec(x[v], k0, k1, k2, k3));
        }
    }
}

extern "C" void kernel_launch(void* const* d_in, const int* in_sizes, int n_in,
                              void* d_out, int out_size) {
    const float* qs    = (const float*)d_in[0];   // [4, 2048, 1024, 4] f32
    const float* amp   = (const float*)d_in[1];   // [24] f32
    const float* phase = (const float*)d_in[2];   // [24] f32
    float* out = (float*)d_out;

    int n4 = out_size / 4;                        // number of quaternions
    int threads = 256;
    int blocks = (n4 + threads * VEC - 1) / (threads * VEC);
    fused_filter_kernel<<<blocks, threads>>>((const float4*)qs, (float4*)out,
                                             amp, phase, n4);
}

// round 12
// speedup vs baseline: 1.0896x; 1.0896x over previous
#include <cuda_runtime.h>
#include <math.h>

// Fused kernel: each block redundantly computes the circulant filter K
// (K[d] = Re(IFFT4(filt))[d]) in warp 0 while the streaming loads are in
// flight, then applies the 4x4 circulant matvec to VEC float4s per thread.
// Streaming cache hints on the bulk load/store; NO register cap (the 8-deep
// load batch needs ~32 regs of payload in flight).
#define VEC 8

__device__ __forceinline__ float4 circ_matvec(float4 q, float k0, float k1,
                                              float k2, float k3) {
    float4 y;
    // out[n] = sum_m x[m] * K[(n-m) & 3]
    y.x = k0 * q.x + k3 * q.y + k2 * q.z + k1 * q.w;
    y.y = k1 * q.x + k0 * q.y + k3 * q.z + k2 * q.w;
    y.z = k2 * q.x + k1 * q.y + k0 * q.z + k3 * q.w;
    y.w = k3 * q.x + k2 * q.y + k1 * q.z + k0 * q.w;
    return y;
}

__global__ void fused_filter_kernel(const float4* __restrict__ in,
                                    float4* __restrict__ out,
                                    const float* __restrict__ amp,
                                    const float* __restrict__ phase,
                                    int n4) {
    __shared__ float sK[4];

    const int span = blockDim.x * VEC;
    const int blk0 = blockIdx.x * span;
    const int base = blk0 + threadIdx.x;
    const bool fast = (blk0 + span <= n4);

    // ---- Issue streaming loads FIRST (independent of K) ----
    float4 x[VEC];
    if (fast) {
        #pragma unroll
        for (int v = 0; v < VEC; v++) x[v] = __ldcs(&in[base + v * blockDim.x]);
    } else {
        #pragma unroll
        for (int v = 0; v < VEC; v++) {
            int i = base + v * blockDim.x;
            if (i < n4) x[v] = __ldcs(&in[i]);
        }
    }

    // ---- Warp 0 computes K while loads are in flight ----
    if (threadIdx.x < 32) {
        const int lane = threadIdx.x;
        const float primes[24] = {2.f,3.f,5.f,7.f,11.f,13.f,17.f,19.f,23.f,29.f,
                                  31.f,37.f,41.f,43.f,47.f,53.f,59.f,61.f,67.f,
                                  71.f,73.f,79.f,83.f,89.f};
        const float PI = 3.14159265358979323846f;

        float re[4] = {0.f, 0.f, 0.f, 0.f};
        float im[4] = {0.f, 0.f, 0.f, 0.f};

        if (lane < 24) {
            float pf = primes[lane] / 89.0f * PI;   // prime freq in [0, pi]
            float a  = amp[lane];
            float ph = phase[lane];
            float cr = __cosf(ph);
            float ci = __sinf(ph);
            #pragma unroll
            for (int j = 0; j < 4; j++) {
                float fi = (float)j * 0.25f * PI;
                float d  = (fi - pf) * 10.0f;       // sigma = 0.1
                float g  = __expf(-0.5f * d * d);
                float w  = a * g;
                re[j] = w * cr;
                im[j] = w * ci;
            }
        }

        // butterfly reduction over the warp
        #pragma unroll
        for (int off = 16; off > 0; off >>= 1) {
            #pragma unroll
            for (int j = 0; j < 4; j++) {
                re[j] += __shfl_xor_sync(0xFFFFFFFFu, re[j], off);
                im[j] += __shfl_xor_sync(0xFFFFFFFFu, im[j], off);
            }
        }

        if (lane == 0) {
            // normalize by max complex magnitude
            float mx = 0.f;
            #pragma unroll
            for (int j = 0; j < 4; j++) {
                float m = sqrtf(re[j] * re[j] + im[j] * im[j]);
                mx = fmaxf(mx, m);
            }
            float inv = 1.0f / (mx + 1e-8f);
            #pragma unroll
            for (int j = 0; j < 4; j++) { re[j] *= inv; im[j] *= inv; }

            // K[d] = (1/4) * Re( sum_j filt[j] * e^{+i*2*pi*j*d/4} )
            // twiddles at multiples of pi/2 exact: cos->{1,0,-1,0}, sin->{0,1,0,-1}
            const float c4[4] = {1.f, 0.f, -1.f, 0.f};
            const float s4[4] = {0.f, 1.f, 0.f, -1.f};
            #pragma unroll
            for (int d = 0; d < 4; d++) {
                float s = 0.f;
                #pragma unroll
                for (int j = 0; j < 4; j++) {
                    int t = (j * d) & 3;
                    s += re[j] * c4[t] - im[j] * s4[t];
                }
                sK[d] = 0.25f * s;
            }
        }
    }
    __syncthreads();

    const float k0 = sK[0], k1 = sK[1], k2 = sK[2], k3 = sK[3];

    // ---- Apply + streaming store ----
    if (fast) {
        #pragma unroll
        for (int v = 0; v < VEC; v++)
            __stcs(&out[base + v * blockDim.x], circ_matvec(x[v], k0, k1, k2, k3));
    } else {
        #pragma unroll
        for (int v = 0; v < VEC; v++) {
            int i = base + v * blockDim.x;
            if (i < n4) __stcs(&out[i], circ_matvec(x[v], k0, k1, k2, k3));
        }
    }
}

extern "C" void kernel_launch(void* const* d_in, const int* in_sizes, int n_in,
                              void* d_out, int out_size) {
    const float* qs    = (const float*)d_in[0];   // [4, 2048, 1024, 4] f32
    const float* amp   = (const float*)d_in[1];   // [24] f32
    const float* phase = (const float*)d_in[2];   // [24] f32
    float* out = (float*)d_out;

    int n4 = out_size / 4;                        // number of quaternions
    int threads = 256;
    int blocks = (n4 + threads * VEC - 1) / (threads * VEC);
    fused_filter_kernel<<<blocks, threads>>>((const float4*)qs, (float4*)out,
                                             amp, phase, n4);
}